// round 10
// baseline (speedup 1.0000x reference)
#include <cuda_runtime.h>
#include <math.h>

#define T_LEN 131072
#define NB 16
#define NCHA 2
#define NSEQ (NB*NCHA)
#define NBS 48
#define DB2L 0.16609640474436813f   // log2(10)/20

// Q layout per plane: t -> chunk c = t>>10 (128), quad q4 = (t&1023)>>2 (256), lane t&3
//   float4 index = q4*128 + c
#define LNC 128
#define Q4  256
#define P4  32768          // float4 per plane

#define BQ_NT 512          // biquad: 512 threads x 256-sample chunks
#define BQ_LEV 9
#define SM_W 16            // smoother warmup chunks (16384 samples)

__device__ float g_xd  [NSEQ*T_LEN];
__device__ float g_low [NSEQ*T_LEN];
__device__ float g_high[NSEQ*T_LEN];
__device__ float g_gin [NBS*T_LEN];     // SIGNED gains (sgn*gain)
__device__ float g_gsm [NBS*T_LEN];     // smoothed gains (raw domain)
__device__ float g_xm  [NSEQ*T_LEN];
__device__ float g_det [NB*T_LEN];      // SIGNED limiter detector
__device__ float g_lg  [NB*T_LEN];
// composed 4-sample warmup maps: 5 intercepts per quad
__device__ float4 g_qmB4[NBS*P4];
__device__ float  g_qmB1[NBS*P4];
__device__ float4 g_qmL4[NB*P4];
__device__ float  g_qmL1[NB*P4];

struct BQ  { float na1, na2, b0, k1, k2; };
struct SMC { float at, rt, A1, A2, AA11, AAX, AA22; };

__device__ __forceinline__ float f_lg2(float x){ float r; asm("lg2.approx.f32 %0,%1;":"=f"(r):"f"(x)); return r; }
__device__ __forceinline__ float f_ex2(float x){ float r; asm("ex2.approx.f32 %0,%1;":"=f"(r):"f"(x)); return r; }

// composed 4-step min-map: intercepts per slope class (Q0..Q4 = A1^4..A2^4)
__device__ __forceinline__ void build_qmap(const SMC& s, float g0, float g1, float g2, float g3,
                                           float4* B, float* b4)
{
    float u11, um, u22, v11, vm, v22;
    { float t0=s.at*g0, t1=s.rt*g0, s0=s.at*g1, s1=s.rt*g1;
      u11=fmaf(s.A1,t0,s0); float a=fmaf(s.A2,t0,s1), b=fmaf(s.A1,t1,s0);
      u22=fmaf(s.A2,t1,s1); um=fminf(a,b); }
    { float t0=s.at*g2, t1=s.rt*g2, s0=s.at*g3, s1=s.rt*g3;
      v11=fmaf(s.A1,t0,s0); float a=fmaf(s.A2,t0,s1), b=fmaf(s.A1,t1,s0);
      v22=fmaf(s.A2,t1,s1); vm=fminf(a,b); }
    float c0 = fmaf(s.AA11,u11,v11);
    float c1 = fminf(fmaf(s.AAX ,u11,vm ), fmaf(s.AA11,um ,v11));
    float c2 = fminf(fmaf(s.AA22,u11,v22), fminf(fmaf(s.AAX,um,vm), fmaf(s.AA11,u22,v11)));
    float c3 = fminf(fmaf(s.AA22,um ,v22), fmaf(s.AAX ,u22,vm ));
    *B  = make_float4(c0, c1, c2, c3);
    *b4 = fmaf(s.AA22,u22,v22);
}

__device__ __forceinline__ SMC make_smc(float at, float rt)
{
    SMC s; s.at=at; s.rt=rt; s.A1=1.f-at; s.A2=1.f-rt;
    s.AA11=s.A1*s.A1; s.AAX=s.A1*s.A2; s.AA22=s.A2*s.A2;
    return s;
}

// ---------------- dist: natural -> Q, tanh drive mix ----------------
__global__ void k_dist(const float* __restrict__ x, const float* __restrict__ drive,
                       const float* __restrict__ dmix)
{
    __shared__ float4 sT[32][33];
    __shared__ float sw, sgd;
    int s = blockIdx.y, b = s >> 1;
    int bx = blockIdx.x;
    int c0 = (bx >> 3) * 32, q0 = (bx & 7) * 32;
    int tx = threadIdx.x, ty = threadIdx.y;
    if (tx == 0 && ty == 0) { sw = dmix[b]; sgd = exp2f(drive[b] * DB2L); }
    __syncthreads();
    float w = sw, gd = sgd, ow = 1.f - w;
    const float4* xin = (const float4*)x + (size_t)s * P4;
    float4 v = __ldg(xin + (c0 + ty) * Q4 + q0 + tx);
#define TL(L) { \
    float z = fminf(fmaxf(v.L * gd, -15.f), 15.f); \
    float e = __expf(2.f * z); \
    float th = __fdividef(e - 1.f, e + 1.f); \
    v.L = fmaf(w, th, ow * v.L); }
    TL(x) TL(y) TL(z) TL(w)
#undef TL
    sT[ty][tx] = v;
    __syncthreads();
    float4* xo = (float4*)g_xd + (size_t)s * P4;
    xo[(q0 + ty) * LNC + c0 + tx] = sT[tx][ty];
}

// ---------------- fused LR4 biquad ----------------
__device__ __forceinline__ void bqstep(float x, float& z1, float& z2, const BQ& c)
{
    float t  = fmaf(c.k1, x, z2);
    float n2 = fmaf(c.na2, z1, c.k2 * x);
    z1 = fmaf(c.na1, z1, t);
    z2 = n2;
}
__device__ __forceinline__ float bqstep_y(float x, float& z1, float& z2, const BQ& c)
{
    float y  = fmaf(c.b0, x, z1);
    float t  = fmaf(c.k1, x, z2);
    float n2 = fmaf(c.na2, z1, c.k2 * x);
    z1 = fmaf(c.na1, z1, t);
    z2 = n2;
    return y;
}

__device__ __forceinline__ float2 ks_scan(float2 my, float2* sF, float (*sP)[4], int tid)
{
    __syncthreads();
#pragma unroll
    for (int lv = 0; lv < BQ_LEV; ++lv) {
        sF[tid] = my;
        __syncthreads();
        int d = 1 << lv;
        if (tid >= d) {
            float2 o = sF[tid - d];
            my.x += sP[lv][0]*o.x + sP[lv][1]*o.y;
            my.y += sP[lv][2]*o.x + sP[lv][3]*o.y;
        }
        __syncthreads();
    }
    sF[tid] = my;
    __syncthreads();
    float2 e = (tid > 0) ? sF[tid-1] : make_float2(0.f, 0.f);
    __syncthreads();
    return e;
}

__global__ void k_bq(const float* __restrict__ locut, const float* __restrict__ hicut)
{
    __shared__ float2 sF[BQ_NT];
    __shared__ float  sP[BQ_LEV][4];
    __shared__ BQ     sCF;
    int blk = blockIdx.x;
    int f = blk >> 5, s = blk & 31, b = s >> 1;
    const float4* in4 = (const float4*)g_xd + (size_t)s * P4;
    float4* out4 = (float4*)(f ? g_high : g_low) + (size_t)s * P4;
    int tid = threadIdx.x;

    if (tid == 0) {
        double cut = f ? (double)hicut[b] : (double)locut[b];
        double w0 = 2.0 * 3.14159265358979323846 * cut / 44100.0;
        double al = sin(w0) * 0.70710678118654752;
        double c  = cos(w0);
        double b0, b1, b2;
        if (f == 0) { b0 = (1.0 - c)*0.5; b1 = 1.0 - c;    b2 = (1.0 - c)*0.5; }
        else        { b0 = (1.0 + c)*0.5; b1 = -(1.0 + c); b2 = (1.0 + c)*0.5; }
        double a0 = 1.0 + al;
        b0 /= a0; b1 /= a0; b2 /= a0;
        double a1 = -2.0*c/a0, a2 = (1.0 - al)/a0;
        sCF.na1 = (float)(-a1); sCF.na2 = (float)(-a2); sCF.b0 = (float)b0;
        sCF.k1 = (float)(b1 - a1*b0); sCF.k2 = (float)(b2 - a2*b0);
        double m00 = -a1, m01 = 1.0, m10 = -a2, m11 = 0.0;
        for (int k = 0; k < 8; ++k) {
            double t00 = m00*m00 + m01*m10, t01 = m00*m01 + m01*m11;
            double t10 = m10*m00 + m11*m10, t11 = m10*m01 + m11*m11;
            m00 = t00; m01 = t01; m10 = t10; m11 = t11;
        }
        for (int lv = 0; lv < BQ_LEV; ++lv) {
            sP[lv][0] = (float)m00; sP[lv][1] = (float)m01;
            sP[lv][2] = (float)m10; sP[lv][3] = (float)m11;
            double t00 = m00*m00 + m01*m10, t01 = m00*m01 + m01*m11;
            double t10 = m10*m00 + m11*m10, t11 = m10*m01 + m11*m11;
            m00 = t00; m01 = t01; m10 = t10; m11 = t11;
        }
    }
    __syncthreads();
    BQ cf = sCF;
    const float4* ip = in4 + (tid & 3) * 64 * LNC + (tid >> 2);
    float4 ring[8];

#define BQ_BODY(STMT) \
    { _Pragma("unroll") for (int j = 0; j < 8; ++j) ring[j] = __ldg(ip + j*LNC); } \
    for (int bs = 0; bs < 56; bs += 8) { \
        _Pragma("unroll") for (int j = 0; j < 8; ++j) { \
            float4 xv = ring[j]; ring[j] = __ldg(ip + (bs + 8 + j)*LNC); \
            int jp = bs + j; (void)jp; STMT; } } \
    { int bs = 56; \
      _Pragma("unroll") for (int j = 0; j < 8; ++j) { \
            float4 xv = ring[j]; int jp = bs + j; (void)jp; STMT; } }

    float z1 = 0.f, z2 = 0.f;
    BQ_BODY({ bqstep(xv.x, z1, z2, cf); bqstep(xv.y, z1, z2, cf);
              bqstep(xv.z, z1, z2, cf); bqstep(xv.w, z1, z2, cf); })
    float2 e1 = ks_scan(make_float2(z1, z2), sF, sP, tid);

    z1 = e1.x; z2 = e1.y;
    float w1 = 0.f, w2 = 0.f;
    BQ_BODY({ bqstep(bqstep_y(xv.x, z1, z2, cf), w1, w2, cf);
              bqstep(bqstep_y(xv.y, z1, z2, cf), w1, w2, cf);
              bqstep(bqstep_y(xv.z, z1, z2, cf), w1, w2, cf);
              bqstep(bqstep_y(xv.w, z1, z2, cf), w1, w2, cf); })
    float2 e2 = ks_scan(make_float2(w1, w2), sF, sP, tid);

    z1 = e1.x; z2 = e1.y; w1 = e2.x; w2 = e2.y;
    float4* op = out4 + (tid & 3) * 64 * LNC + (tid >> 2);
    BQ_BODY({ float4 r;
              r.x = bqstep_y(bqstep_y(xv.x, z1, z2, cf), w1, w2, cf);
              r.y = bqstep_y(bqstep_y(xv.y, z1, z2, cf), w1, w2, cf);
              r.z = bqstep_y(bqstep_y(xv.z, z1, z2, cf), w1, w2, cf);
              r.w = bqstep_y(bqstep_y(xv.w, z1, z2, cf), w1, w2, cf);
              op[jp*LNC] = r; })
#undef BQ_BODY
}

// ---------------- band gain + warmup-map emission ----------------
struct GP { float ct, sc, et, se; };
__device__ __forceinline__ float comp_gain(float det, const GP& p)
{
    float xdb = 6.0205999132796239f * f_lg2(fmaxf(det, 1e-7f));
    float gdb = fminf(fminf(p.sc * (p.ct - xdb), p.se * (p.et - xdb)), 0.f);
    return f_ex2(gdb * DB2L);
}

__global__ void k_bandgain(const float* __restrict__ ct, const float* __restrict__ cr,
                           const float* __restrict__ et, const float* __restrict__ er,
                           const float* __restrict__ atms, const float* __restrict__ rtms)
{
    __shared__ GP  sp[3];
    __shared__ SMC sc[3];
    __shared__ float ssg[3];
    int b = blockIdx.y;
    int tid = threadIdx.x;
    if (tid < 3) {
        int idx = b*3 + tid;
        GP g; g.ct = ct[idx]; g.sc = 1.f - 1.f/cr[idx];
        g.et = et[idx]; g.se = 1.f - 1.f/er[idx];
        sp[tid] = g;
        float at = 1.f - __expf(-2200.f/(atms[idx]*44100.f));
        float rt = 1.f - __expf(-2200.f/(rtms[idx]*44100.f));
        sc[tid] = make_smc(at, rt);
        ssg[tid] = (at >= rt) ? 1.f : -1.f;   // attack_on_rise=False -> min iff at>=rt
    }
    __syncthreads();
    int i = blockIdx.x * blockDim.x + tid;
    size_t p0 = (size_t)(b*2) * P4, p1 = p0 + P4;
    float4 x0 = ((const float4*)g_xd)[p0 + i],  x1 = ((const float4*)g_xd)[p1 + i];
    float4 l0 = ((const float4*)g_low)[p0 + i], l1 = ((const float4*)g_low)[p1 + i];
    float4 h0 = ((const float4*)g_high)[p0 + i],h1 = ((const float4*)g_high)[p1 + i];
    float4 gl, gm, gh;
#define GL(L) { float ls = l0.L + l1.L, hs = h0.L + h1.L, xs = x0.L + x1.L; \
    gl.L = comp_gain(fabsf(ls), sp[0]); \
    gm.L = comp_gain(fabsf(xs - ls - hs), sp[1]); \
    gh.L = comp_gain(fabsf(hs), sp[2]); }
    GL(x) GL(y) GL(z) GL(w)
#undef GL
#define EMIT(K, G) { \
    float sg = ssg[K]; SMC s = sc[K]; \
    float4 gg; gg.x = sg*G.x; gg.y = sg*G.y; gg.z = sg*G.z; gg.w = sg*G.w; \
    size_t pl = (size_t)(K*NB + b); \
    ((float4*)g_gin)[pl*P4 + i] = gg; \
    float4 B; float b4v; build_qmap(s, gg.x, gg.y, gg.z, gg.w, &B, &b4v); \
    g_qmB4[pl*P4 + i] = B; g_qmB1[pl*P4 + i] = b4v; }
    EMIT(0, gl) EMIT(1, gm) EMIT(2, gh)
#undef EMIT
}

// ---------------- smoothing: composed-map warmup + exact store segment ----------------
__device__ __forceinline__ float warm_seg(const float4* __restrict__ m4,
                                          const float* __restrict__ m1, float h,
                                          float Q0, float Q1, float Q2, float Q3, float Q4v)
{
    float4 rb[16]; float rc[16];
#pragma unroll
    for (int j = 0; j < 16; ++j) { rb[j] = __ldg(m4 + j*LNC); rc[j] = __ldg(m1 + j*LNC); }
#define WQ h = fminf(fminf(fmaf(Q0,h,B.x), fmaf(Q1,h,B.y)), \
                     fminf(fmaf(Q2,h,B.z), fminf(fmaf(Q3,h,B.w), fmaf(Q4v,h,b4))));
    for (int bs = 0; bs < Q4-16; bs += 16) {
#pragma unroll
        for (int j = 0; j < 16; ++j) {
            float4 B = rb[j]; float b4 = rc[j];
            rb[j] = __ldg(m4 + (bs + 16 + j)*LNC);
            rc[j] = __ldg(m1 + (bs + 16 + j)*LNC);
            WQ
        }
    }
#pragma unroll
    for (int j = 0; j < 16; ++j) { float4 B = rb[j]; float b4 = rc[j]; WQ }
#undef WQ
    return h;
}

__device__ __forceinline__ float pair_min(float h, float g0, float g1, float* h1, const SMC& s)
{
    float t0 = s.at*g0, t1 = s.rt*g0, s0 = s.at*g1, s1 = s.rt*g1;
    float u11 = fmaf(s.A1,t0,s0), u21 = fmaf(s.A2,t0,s1);
    float u12 = fmaf(s.A1,t1,s0), u22 = fmaf(s.A2,t1,s1);
    float um  = fminf(u21, u12);
    *h1 = fminf(fmaf(s.A1,h,t0), fmaf(s.A2,h,t1));
    return fminf(fmaf(s.AA11,h,u11), fminf(fmaf(s.AAX,h,um), fmaf(s.AA22,h,u22)));
}

template<bool LIM>
__device__ __forceinline__ void store_seg(const float4* __restrict__ sp4, float4* __restrict__ dp,
                                          float h, const SMC& s, float sgn, float lt)
{
    float4 ring[16];
#pragma unroll
    for (int j = 0; j < 16; ++j) ring[j] = __ldg(sp4 + j*LNC);
#define SQ { float h1a, h1b; \
    float hA = pair_min(h, gv.x, gv.y, &h1a, s); \
    h = pair_min(hA, gv.z, gv.w, &h1b, s); \
    float4 o; \
    if (LIM) { \
        o.x = fminf(1.f, __fdividef(lt, fmaxf(sgn*h1a, 1e-7f))); \
        o.y = fminf(1.f, __fdividef(lt, fmaxf(sgn*hA , 1e-7f))); \
        o.z = fminf(1.f, __fdividef(lt, fmaxf(sgn*h1b, 1e-7f))); \
        o.w = fminf(1.f, __fdividef(lt, fmaxf(sgn*h  , 1e-7f))); \
    } else { o.x = sgn*h1a; o.y = sgn*hA; o.z = sgn*h1b; o.w = sgn*h; } \
    dp[jp*LNC] = o; }
    for (int bs = 0; bs < Q4-16; bs += 16) {
#pragma unroll
        for (int j = 0; j < 16; ++j) {
            float4 gv = ring[j]; ring[j] = __ldg(sp4 + (bs + 16 + j)*LNC);
            int jp = bs + j;
            SQ
        }
    }
    { int bs = Q4-16;
#pragma unroll
      for (int j = 0; j < 16; ++j) { float4 gv = ring[j]; int jp = bs + j; SQ } }
#undef SQ
}

__global__ void k_smooth_band(const float* __restrict__ atms, const float* __restrict__ rtms)
{
    int seq = blockIdx.x, c = threadIdx.x;      // 48 x 128
    int band = seq >> 4, b = seq & 15;
    int idx = b*3 + band;
    float at = 1.f - __expf(-2200.f/(atms[idx]*44100.f));
    float rt = 1.f - __expf(-2200.f/(rtms[idx]*44100.f));
    float sgn = (at >= rt) ? 1.f : -1.f;
    SMC s = make_smc(at, rt);
    float Q0 = s.AA11*s.AA11, Q1 = s.AA11*s.AAX, Q2 = s.AAX*s.AAX,
          Q3 = s.AAX*s.AA22, Q4v = s.AA22*s.AA22;
    const float4* m4 = g_qmB4 + (size_t)seq*P4;
    const float*  m1 = g_qmB1 + (size_t)seq*P4;
    float h = sgn;    // f init = 1
#pragma unroll 1
    for (int seg = 0; seg < SM_W; ++seg) {
        int cc = c - SM_W + seg;
        if (cc >= 0) h = warm_seg(m4 + cc, m1 + cc, h, Q0, Q1, Q2, Q3, Q4v);
    }
    const float4* gin = (const float4*)(g_gin + (size_t)seq*T_LEN) + c;
    float4*       gsm = (float4*)(g_gsm + (size_t)seq*T_LEN) + c;
    store_seg<false>(gin, gsm, h, s, sgn, 0.f);
}

__global__ void k_smooth_lim(const float* __restrict__ lth, const float* __restrict__ lat,
                             const float* __restrict__ lrt)
{
    int b = blockIdx.x, c = threadIdx.x;        // 16 x 128
    float at = 1.f - __expf(-2200.f/(lat[b]*44100.f));
    float rt = 1.f - __expf(-2200.f/(lrt[b]*44100.f));
    float sgn = (at <= rt) ? 1.f : -1.f;        // attack_on_rise=True -> min iff at<=rt
    float lt = exp2f(lth[b] * DB2L);
    SMC s = make_smc(at, rt);
    float Q0 = s.AA11*s.AA11, Q1 = s.AA11*s.AAX, Q2 = s.AAX*s.AAX,
          Q3 = s.AAX*s.AA22, Q4v = s.AA22*s.AA22;
    const float4* m4 = g_qmL4 + (size_t)b*P4;
    const float*  m1 = g_qmL1 + (size_t)b*P4;
    float h = 0.f;    // f init = 0
#pragma unroll 1
    for (int seg = 0; seg < SM_W; ++seg) {
        int cc = c - SM_W + seg;
        if (cc >= 0) h = warm_seg(m4 + cc, m1 + cc, h, Q0, Q1, Q2, Q3, Q4v);
    }
    const float4* det = (const float4*)(g_det + (size_t)b*T_LEN) + c;
    float4*       lg  = (float4*)(g_lg + (size_t)b*T_LEN) + c;
    store_seg<true>(det, lg, h, s, sgn, lt);
}

// ---------------- mix + limiter detector (+ limiter maps) ----------------
__global__ void k_mix(const float* __restrict__ mbmix, const float* __restrict__ lat,
                      const float* __restrict__ lrt)
{
    __shared__ SMC sl;
    __shared__ float slsg;
    int b = blockIdx.y;
    int tid = threadIdx.x;
    if (tid == 0) {
        float at = 1.f - __expf(-2200.f/(lat[b]*44100.f));
        float rt = 1.f - __expf(-2200.f/(lrt[b]*44100.f));
        sl = make_smc(at, rt);
        slsg = (at <= rt) ? 1.f : -1.f;
    }
    __syncthreads();
    float mb = __ldg(mbmix + b), om = 1.f - mb;
    int i = blockIdx.x * blockDim.x + tid;
    size_t p0 = (size_t)(b*2) * P4, p1 = p0 + P4;
    float4 x0 = ((const float4*)g_xd)[p0 + i],  x1 = ((const float4*)g_xd)[p1 + i];
    float4 l0 = ((const float4*)g_low)[p0 + i], l1 = ((const float4*)g_low)[p1 + i];
    float4 h0 = ((const float4*)g_high)[p0 + i],h1 = ((const float4*)g_high)[p1 + i];
    float4 gl = ((const float4*)g_gsm)[(size_t)(0*NB + b)*P4 + i];
    float4 gm = ((const float4*)g_gsm)[(size_t)(1*NB + b)*P4 + i];
    float4 gh = ((const float4*)g_gsm)[(size_t)(2*NB + b)*P4 + i];
    float4 m0, m1, dt;
#define ML(L) { \
    float mid0 = x0.L - l0.L - h0.L; \
    float y0 = l0.L*gl.L + mid0*gm.L + h0.L*gh.L; \
    float a0 = mb*y0 + om*x0.L; \
    float mid1 = x1.L - l1.L - h1.L; \
    float y1 = l1.L*gl.L + mid1*gm.L + h1.L*gh.L; \
    float a1 = mb*y1 + om*x1.L; \
    m0.L = a0; m1.L = a1; dt.L = fabsf(a0 + a1); }
    ML(x) ML(y) ML(z) ML(w)
#undef ML
    ((float4*)g_xm)[p0 + i] = m0;
    ((float4*)g_xm)[p1 + i] = m1;
    float sg = slsg;
    float4 gg; gg.x = sg*dt.x; gg.y = sg*dt.y; gg.z = sg*dt.z; gg.w = sg*dt.w;
    ((float4*)g_det)[(size_t)b*P4 + i] = gg;
    float4 B; float b4v;
    build_qmap(sl, gg.x, gg.y, gg.z, gg.w, &B, &b4v);
    g_qmL4[(size_t)b*P4 + i] = B;
    g_qmL1[(size_t)b*P4 + i] = b4v;
}

// ---------------- final: Q -> natural, apply limiter gain ----------------
__global__ void k_final(float* __restrict__ out)
{
    __shared__ float4 sA[32][33], sB[32][33];
    int b = blockIdx.y;
    int bx = blockIdx.x;
    int c0 = (bx >> 3) * 32, q0 = (bx & 7) * 32;
    int tx = threadIdx.x, ty = threadIdx.y;
    size_t A = (size_t)(q0 + ty) * LNC + c0 + tx;
    const float4* lg4 = (const float4*)g_lg + (size_t)b * P4;
    const float4* xm4 = (const float4*)g_xm;
    float4 g  = __ldg(lg4 + A);
    float4 m0 = __ldg(xm4 + (size_t)(b*2)   * P4 + A);
    float4 m1 = __ldg(xm4 + (size_t)(b*2+1) * P4 + A);
    m0.x *= g.x; m0.y *= g.y; m0.z *= g.z; m0.w *= g.w;
    m1.x *= g.x; m1.y *= g.y; m1.z *= g.z; m1.w *= g.w;
    sA[tx][ty] = m0;
    sB[tx][ty] = m1;
    __syncthreads();
    float4* o0 = (float4*)out + (size_t)(b*2) * P4;
    float4* o1 = o0 + P4;
    size_t N = (size_t)(c0 + ty) * Q4 + q0 + tx;
    o0[N] = sA[ty][tx];
    o1[N] = sB[ty][tx];
}

// ---------------- launcher ----------------
extern "C" void kernel_launch(void* const* d_in, const int* in_sizes, int n_in,
                              void* d_out, int out_size)
{
    const float* x     = (const float*)d_in[0];
    const float* drive = (const float*)d_in[1];
    const float* dmix  = (const float*)d_in[2];
    const float* locut = (const float*)d_in[3];
    const float* hicut = (const float*)d_in[4];
    const float* mbmix = (const float*)d_in[5];
    const float* ct    = (const float*)d_in[6];
    const float* cr    = (const float*)d_in[7];
    const float* et    = (const float*)d_in[8];
    const float* er    = (const float*)d_in[9];
    const float* atms  = (const float*)d_in[10];
    const float* rtms  = (const float*)d_in[11];
    const float* lth   = (const float*)d_in[12];
    const float* lat   = (const float*)d_in[13];
    const float* lrt   = (const float*)d_in[14];
    (void)in_sizes; (void)n_in; (void)out_size;

    dim3 tile(32, 32);
    k_dist<<<dim3(32, NSEQ), tile>>>(x, drive, dmix);
    k_bq<<<64, BQ_NT>>>(locut, hicut);
    k_bandgain<<<dim3(128, NB), 256>>>(ct, cr, et, er, atms, rtms);
    k_smooth_band<<<NBS, LNC>>>(atms, rtms);
    k_mix<<<dim3(128, NB), 256>>>(mbmix, lat, lrt);
    k_smooth_lim<<<NB, LNC>>>(lth, lat, lrt);
    k_final<<<dim3(32, NB), tile>>>((float*)d_out);
}